// round 8
// baseline (speedup 1.0000x reference)
#include <cuda_runtime.h>

#define NN 50000
#define EE 1600000
#define H  64
#define TG  32      // edges per group-tile
#define NGB 4       // groups per block
#define TTH 256     // threads per edge block
#define RL3 32      // s_t row length
#define NTG (EE/TG) // 50000 group-tiles

typedef unsigned long long ull;

// ---------------- scratch (device globals; no allocation allowed) ----------------
__device__ float g_h[NN*H];
__device__ float g_A[NN*H];      // h@Wa + e_b1
__device__ float g_B[NN*H];      // h@Wb
__device__ float g_magg[NN*H];   // segment-summed messages
__device__ float g_cagg4[NN*4];  // segment-summed coord updates (padded)
__device__ float g_vel[NN];      // vel_scale
__device__ float g_deg[NN];      // clipped out-degree (float)
__device__ int   g_cnt[NN];      // raw out-degree
__device__ int   g_off[NN];      // fill cursors
__device__ float g_x4[NN*4];     // padded coords
__device__ float g_v4[NN*4];     // padded velocities
// r-sorted edge arrays
__device__ int    g_er[EE];
__device__ int    g_ec[EE];
__device__ float2 g_ea2[EE];

__device__ __forceinline__ float silu_f(float x){
    float th;
    asm("tanh.approx.f32 %0, %1;" : "=f"(th) : "f"(0.5f*x));
    return 0.5f*x*th + 0.5f*x;
}
__device__ __forceinline__ ull pack2(float x, float y){
    ull r; asm("mov.b64 %0, {%1,%2};" : "=l"(r) : "f"(x), "f"(y)); return r;
}
__device__ __forceinline__ float2 unpack2(ull p){
    float2 r; asm("mov.b64 {%0,%1}, %2;" : "=f"(r.x), "=f"(r.y) : "l"(p)); return r;
}
__device__ __forceinline__ void fma2(ull& d, ull a, ull b){
    asm("fma.rn.f32x2 %0, %1, %2, %0;" : "+l"(d) : "l"(a), "l"(b));
}
__device__ __forceinline__ void red4(float* p, float a, float b, float c, float d){
    asm volatile("red.global.add.v4.f32 [%0], {%1,%2,%3,%4};"
                 :: "l"(p), "f"(a), "f"(b), "f"(c), "f"(d) : "memory");
}
__device__ __forceinline__ void pf_l1(const float* p){
    asm volatile("prefetch.global.L1 [%0];" :: "l"(p));
}

// ---------------- init ------------------------------------------------------------
__global__ void k_init(const float* __restrict__ his, const float* __restrict__ emb_w,
                       const float* __restrict__ emb_b, const float* __restrict__ x,
                       const float* __restrict__ v){
    int idx = blockIdx.x*blockDim.x + threadIdx.x;
    if (idx < NN*H){
        int n = idx >> 6, j = idx & 63;
        float acc = emb_b[j];
        #pragma unroll
        for (int k=0;k<16;k++) acc += his[n*16+k]*emb_w[k*H+j];
        g_h[idx] = acc;
    }
    if (idx < NN){
        g_x4[idx*4+0]=x[idx*3+0]; g_x4[idx*4+1]=x[idx*3+1]; g_x4[idx*4+2]=x[idx*3+2]; g_x4[idx*4+3]=0.f;
        g_v4[idx*4+0]=v[idx*3+0]; g_v4[idx*4+1]=v[idx*3+1]; g_v4[idx*4+2]=v[idx*3+2]; g_v4[idx*4+3]=0.f;
        g_cnt[idx] = 0;
    }
}

__global__ void k_deg(const int* __restrict__ edges){
    int e = blockIdx.x*blockDim.x + threadIdx.x;
    if (e < EE) atomicAdd(&g_cnt[edges[e]], 1);
}

// single-block exclusive scan over g_cnt -> g_off; also g_deg = max(cnt,1)
__global__ void k_scan(){
    __shared__ int s_part[1024];
    int tid = threadIdx.x;
    const int CH = (NN + 1023)/1024;   // 49
    int base = tid*CH;
    int sum = 0;
    #pragma unroll 7
    for (int i=0;i<CH;i++){ int n=base+i; if(n<NN) sum += g_cnt[n]; }
    s_part[tid] = sum;
    __syncthreads();
    for (int off=1; off<1024; off<<=1){
        int t = (tid >= off) ? s_part[tid-off] : 0;
        __syncthreads();
        s_part[tid] += t;
        __syncthreads();
    }
    int run = s_part[tid] - sum;
    for (int i=0;i<CH;i++){
        int n = base+i;
        if (n < NN){
            int c = g_cnt[n];
            g_off[n] = run;
            g_deg[n] = (c > 0) ? (float)c : 1.0f;
            run += c;
        }
    }
}

__global__ void k_fill(const int* __restrict__ edges, const float* __restrict__ edge_attr){
    int e = blockIdx.x*blockDim.x + threadIdx.x;
    if (e < EE){
        int r = edges[e];
        int pos = atomicAdd(&g_off[r], 1);
        g_er[pos] = r;
        g_ec[pos] = edges[EE+e];
        g_ea2[pos] = ((const float2*)edge_attr)[e];
    }
}

// ------ layer-0 node precompute: A,B, vel_scale; zero aggs ------------------------
__global__ void k_prevel(const float* __restrict__ e_w1, const float* __restrict__ e_b1,
                         const float* __restrict__ v_w1, const float* __restrict__ v_b1,
                         const float* __restrict__ v_w2, const float* __restrict__ v_b2){
    extern __shared__ float sp[];
    float* s_ew  = sp;            // 128x64
    float* s_vw  = sp + 8192;     // 64x64
    float* s_eb1 = sp + 12288;
    float* s_vb1 = sp + 12352;
    float* s_vw2 = sp + 12416;
    int tid = threadIdx.x;
    for (int i=tid; i<8192; i+=blockDim.x) s_ew[i] = e_w1[i];
    for (int i=tid; i<4096; i+=blockDim.x) s_vw[i] = v_w1[i];
    if (tid < 64){ s_eb1[tid]=e_b1[tid]; s_vb1[tid]=v_b1[tid]; s_vw2[tid]=v_w2[tid]; }
    __syncthreads();
    int lane = tid & 31, warp = tid >> 5;
    int j0 = 2*lane;
    int wpb = blockDim.x >> 5;
    float vb2 = v_b2[0];
    for (int n = blockIdx.x*wpb + warp; n < NN; n += gridDim.x*wpb){
        float h0 = g_h[n*H+j0], h1 = g_h[n*H+j0+1];
        float a0 = s_eb1[j0], a1 = s_eb1[j0+1];
        float b0 = 0.f, b1 = 0.f;
        float t0 = s_vb1[j0], t1 = s_vb1[j0+1];
        #pragma unroll
        for (int k=0;k<H;k++){
            float hk = __shfl_sync(0xffffffffu, (k&1)?h1:h0, k>>1);
            float2 wa = *(const float2*)&s_ew[k*H+j0];
            float2 wb = *(const float2*)&s_ew[(H+k)*H+j0];
            float2 wv = *(const float2*)&s_vw[k*H+j0];
            a0 += hk*wa.x; a1 += hk*wa.y;
            b0 += hk*wb.x; b1 += hk*wb.y;
            t0 += hk*wv.x; t1 += hk*wv.y;
        }
        *(float2*)&g_A[n*H+j0]    = make_float2(a0,a1);
        *(float2*)&g_B[n*H+j0]    = make_float2(b0,b1);
        *(float2*)&g_magg[n*H+j0] = make_float2(0.f,0.f);
        float p = silu_f(t0)*s_vw2[j0] + silu_f(t1)*s_vw2[j0+1];
        #pragma unroll
        for (int o=16;o>0;o>>=1) p += __shfl_xor_sync(0xffffffffu, p, o);
        if (lane == 0){
            g_vel[n] = p + vb2;
            *(float4*)&g_cagg4[n*4] = make_float4(0.f,0.f,0.f,0.f);
        }
    }
}

// ------- edge kernel: 4x64-thread groups, 32-edge r-sorted tiles, run-agg scatter -
__global__ void __launch_bounds__(TTH, 3)
k_edge(const float* __restrict__ e_w1, const float* __restrict__ e_w2,
       const float* __restrict__ e_b2, const float* __restrict__ c_w1,
       const float* __restrict__ c_b1, const float* __restrict__ c_w2){
    extern __shared__ float sm[];
    float* s_w2  = sm;              // 4096 (block-shared, read-only)
    float* s_c1  = sm + 4096;       // 4096
    float* s_wr  = sm + 8192;       // 64
    float* s_we0 = sm + 8256;
    float* s_we1 = sm + 8320;
    float* s_eb2 = sm + 8384;
    float* s_cb1 = sm + 8448;
    float* s_cw2 = sm + 8512;       // .. 8576
    int tid = threadIdx.x;
    int g    = tid >> 6;            // group 0..3
    int gtid = tid & 63;
    float* gb   = sm + 8576 + g*2432;
    float* s_t  = gb;               // 64*RL3 = 2048
    float* s_gp = gb + 2048;        // 8*32 = 256
    float* s_dx = gb + 2304;        // 32
    float* s_dy = gb + 2336;
    float* s_dz = gb + 2368;
    int*   s_r  = (int*)(gb + 2400);// 32

    for (int i=tid; i<4096; i+=TTH){ s_w2[i] = e_w2[i]; s_c1[i] = c_w1[i]; }
    if (tid < 64){
        s_wr [tid] = e_w1[128*H+tid];
        s_we0[tid] = e_w1[129*H+tid];
        s_we1[tid] = e_w1[130*H+tid];
        s_eb2[tid] = e_b2[tid];
        s_cb1[tid] = c_b1[tid];
        s_cw2[tid] = c_w2[tid];
    }
    __syncthreads();

    int el = gtid & 31, hf = gtid >> 5;   // P1 mapping (2 threads/edge)
    int eg = gtid & 7,  og = gtid >> 3;   // GEMM mapping: 4 edges x 8 outputs
    int bar = g + 1;
    const int estep = gridDim.x*NGB*TG;

    for (int tile = blockIdx.x*NGB + g; tile < NTG; tile += gridDim.x*NGB){
        // ---- P1: gather + first-layer pre + silu -> s_t[k][e]; prefetch next ----
        {
            int e = tile*TG + el;
            int r = g_er[e], c = g_ec[e];
            int en = e + estep;
            if (en < EE){
                int rn = g_er[en], cn = g_ec[en];
                pf_l1(g_A + rn*H + hf*32);
                pf_l1(g_B + cn*H + hf*32);
            }
            float4 xr = *(const float4*)&g_x4[r*4];
            float4 xc = *(const float4*)&g_x4[c*4];
            float dx = xr.x-xc.x, dy = xr.y-xc.y, dz = xr.z-xc.z;
            float radial = dx*dx + dy*dy + dz*dz;
            float2 ea = g_ea2[e];
            const float4* Ap = (const float4*)(g_A + r*H + hf*32);
            const float4* Bp = (const float4*)(g_B + c*H + hf*32);
            int kb = hf*32;
            #pragma unroll
            for (int q=0;q<8;q++){
                float4 a = Ap[q], b = Bp[q];
                int k = kb + 4*q;
                float4 w1 = *(const float4*)&s_wr [k];
                float4 w2 = *(const float4*)&s_we0[k];
                float4 w3 = *(const float4*)&s_we1[k];
                s_t[(k+0)*RL3+el] = silu_f(a.x + b.x + radial*w1.x + ea.x*w2.x + ea.y*w3.x);
                s_t[(k+1)*RL3+el] = silu_f(a.y + b.y + radial*w1.y + ea.x*w2.y + ea.y*w3.y);
                s_t[(k+2)*RL3+el] = silu_f(a.z + b.z + radial*w1.z + ea.x*w2.z + ea.y*w3.z);
                s_t[(k+3)*RL3+el] = silu_f(a.w + b.w + radial*w1.w + ea.x*w2.w + ea.y*w3.w);
            }
            if (!hf){ s_r[el]=r; s_dx[el]=dx; s_dy[el]=dy; s_dz[el]=dz; }
        }
        asm volatile("bar.sync %0, 64;" :: "r"(bar) : "memory");

        // ---- P2: GEMM1  M[e][j] = sum_k s_t[k][e] * w2[k][j] ----
        ull acc[16];
        {
            ull b0 = *(const ull*)&s_eb2[og*8+0];
            ull b1 = *(const ull*)&s_eb2[og*8+2];
            ull b2 = *(const ull*)&s_eb2[og*8+4];
            ull b3 = *(const ull*)&s_eb2[og*8+6];
            #pragma unroll
            for (int e4=0;e4<4;e4++){ acc[e4*4]=b0; acc[e4*4+1]=b1; acc[e4*4+2]=b2; acc[e4*4+3]=b3; }
            const float* tp = s_t + eg*4;
            const float* wk = s_w2 + og*8;
            #pragma unroll 8
            for (int k=0;k<64;k++){
                float4 tv = *(const float4*)(tp + k*RL3);
                ulonglong2 wa = *(const ulonglong2*)(wk + k*64);
                ulonglong2 wb = *(const ulonglong2*)(wk + k*64 + 4);
                ull t0 = pack2(tv.x,tv.x), t1 = pack2(tv.y,tv.y);
                ull t2 = pack2(tv.z,tv.z), t3 = pack2(tv.w,tv.w);
                fma2(acc[0],  t0, wa.x); fma2(acc[1],  t0, wa.y); fma2(acc[2],  t0, wb.x); fma2(acc[3],  t0, wb.y);
                fma2(acc[4],  t1, wa.x); fma2(acc[5],  t1, wa.y); fma2(acc[6],  t1, wb.x); fma2(acc[7],  t1, wb.y);
                fma2(acc[8],  t2, wa.x); fma2(acc[9],  t2, wa.y); fma2(acc[10], t2, wb.x); fma2(acc[11], t2, wb.y);
                fma2(acc[12], t3, wa.x); fma2(acc[13], t3, wa.y); fma2(acc[14], t3, wb.x); fma2(acc[15], t3, wb.y);
            }
        }
        asm volatile("bar.sync %0, 64;" :: "r"(bar) : "memory");

        // ---- P3: silu(M), store ms -> s_t[j][e], run-aggregated scatter to m_agg -
        {
            float ms[4][8];
            #pragma unroll
            for (int e4=0;e4<4;e4++){
                #pragma unroll
                for (int jp=0;jp<4;jp++){
                    float2 f = unpack2(acc[e4*4+jp]);
                    ms[e4][2*jp]   = silu_f(f.x);
                    ms[e4][2*jp+1] = silu_f(f.y);
                }
            }
            #pragma unroll
            for (int j=0;j<8;j++){
                *(float4*)&s_t[(og*8+j)*RL3 + eg*4] =
                    make_float4(ms[0][j], ms[1][j], ms[2][j], ms[3][j]);
            }
            int rr[4] = {s_r[eg*4+0], s_r[eg*4+1], s_r[eg*4+2], s_r[eg*4+3]};
            int rh = 0;
            #pragma unroll
            for (int e4=1;e4<4;e4++){
                if (rr[e4] == rr[rh]){
                    #pragma unroll
                    for (int j=0;j<8;j++) ms[rh][j] += ms[e4][j];
                } else {
                    float* mp = &g_magg[rr[rh]*H + og*8];
                    red4(mp,   ms[rh][0], ms[rh][1], ms[rh][2], ms[rh][3]);
                    red4(mp+4, ms[rh][4], ms[rh][5], ms[rh][6], ms[rh][7]);
                    rh = e4;
                }
            }
            float* mp = &g_magg[rr[rh]*H + og*8];
            red4(mp,   ms[rh][0], ms[rh][1], ms[rh][2], ms[rh][3]);
            red4(mp+4, ms[rh][4], ms[rh][5], ms[rh][6], ms[rh][7]);
        }
        asm volatile("bar.sync %0, 64;" :: "r"(bar) : "memory");

        // ---- P4: GEMM2  U[e][j] = sum_k ms[k][e] * c1[k][j]; partial g ----
        {
            ull b0 = *(const ull*)&s_cb1[og*8+0];
            ull b1 = *(const ull*)&s_cb1[og*8+2];
            ull b2 = *(const ull*)&s_cb1[og*8+4];
            ull b3 = *(const ull*)&s_cb1[og*8+6];
            #pragma unroll
            for (int e4=0;e4<4;e4++){ acc[e4*4]=b0; acc[e4*4+1]=b1; acc[e4*4+2]=b2; acc[e4*4+3]=b3; }
            const float* tp = s_t + eg*4;
            const float* wk = s_c1 + og*8;
            #pragma unroll 8
            for (int k=0;k<64;k++){
                float4 tv = *(const float4*)(tp + k*RL3);
                ulonglong2 wa = *(const ulonglong2*)(wk + k*64);
                ulonglong2 wb = *(const ulonglong2*)(wk + k*64 + 4);
                ull t0 = pack2(tv.x,tv.x), t1 = pack2(tv.y,tv.y);
                ull t2 = pack2(tv.z,tv.z), t3 = pack2(tv.w,tv.w);
                fma2(acc[0],  t0, wa.x); fma2(acc[1],  t0, wa.y); fma2(acc[2],  t0, wb.x); fma2(acc[3],  t0, wb.y);
                fma2(acc[4],  t1, wa.x); fma2(acc[5],  t1, wa.y); fma2(acc[6],  t1, wb.x); fma2(acc[7],  t1, wb.y);
                fma2(acc[8],  t2, wa.x); fma2(acc[9],  t2, wa.y); fma2(acc[10], t2, wb.x); fma2(acc[11], t2, wb.y);
                fma2(acc[12], t3, wa.x); fma2(acc[13], t3, wa.y); fma2(acc[14], t3, wb.x); fma2(acc[15], t3, wb.y);
            }
            float gp[4];
            #pragma unroll
            for (int e4=0;e4<4;e4++){
                float s = 0.f;
                #pragma unroll
                for (int jp=0;jp<4;jp++){
                    float2 f = unpack2(acc[e4*4+jp]);
                    s += silu_f(f.x)*s_cw2[og*8+2*jp] + silu_f(f.y)*s_cw2[og*8+2*jp+1];
                }
                gp[e4] = s;
            }
            *(float4*)&s_gp[og*32 + eg*4] = make_float4(gp[0],gp[1],gp[2],gp[3]);
        }
        asm volatile("bar.sync %0, 64;" :: "r"(bar) : "memory");

        // ---- P5: reduce g across out-groups; segmented coord scatter ----
        if (gtid < 32){
            float gg = 0.f;
            #pragma unroll
            for (int o=0;o<8;o++) gg += s_gp[o*32 + gtid];
            int r = s_r[gtid];
            float cx = s_dx[gtid]*gg, cy = s_dy[gtid]*gg, cz = s_dz[gtid]*gg;
            unsigned fm = 0xffffffffu;
            #pragma unroll
            for (int off=1; off<32; off<<=1){
                int ro   = __shfl_down_sync(fm, r,  off);
                float xo = __shfl_down_sync(fm, cx, off);
                float yo = __shfl_down_sync(fm, cy, off);
                float zo = __shfl_down_sync(fm, cz, off);
                if (gtid + off < 32 && ro == r){ cx += xo; cy += yo; cz += zo; }
            }
            int rp = __shfl_up_sync(fm, r, 1);
            if (gtid == 0 || rp != r)
                red4(&g_cagg4[r*4], cx, cy, cz, 0.f);
        }
        asm volatile("bar.sync %0, 64;" :: "r"(bar) : "memory");
    }
}

// -------- fused node MLP + state update + NEXT-layer precompute -------------------
__global__ void k_node(const float* __restrict__ n_w1, const float* __restrict__ n_b1,
                       const float* __restrict__ n_w2, const float* __restrict__ n_b2,
                       const float* __restrict__ e_w1, const float* __restrict__ e_b1,
                       const float* __restrict__ v_w1, const float* __restrict__ v_b1,
                       const float* __restrict__ v_w2, const float* __restrict__ v_b2,
                       int do_pre){
    extern __shared__ float sn[];
    float* s_w1  = sn;            // 128x64 node W1
    float* s_w2  = sn + 8192;     // 64x64  node W2
    float* s_ew  = sn + 12288;    // 128x64 edge W1 (A|B halves)
    float* s_vw  = sn + 20480;    // 64x64  vel W1
    float* s_b1  = sn + 24576;
    float* s_b2  = sn + 24640;
    float* s_eb1 = sn + 24704;
    float* s_vb1 = sn + 24768;
    float* s_vw2 = sn + 24832;    // .. 24896 floats = 99584 B
    int tid = threadIdx.x;
    for (int i=tid; i<8192; i+=blockDim.x) s_w1[i] = n_w1[i];
    for (int i=tid; i<4096; i+=blockDim.x) s_w2[i] = n_w2[i];
    if (do_pre){
        for (int i=tid; i<8192; i+=blockDim.x) s_ew[i] = e_w1[i];
        for (int i=tid; i<4096; i+=blockDim.x) s_vw[i] = v_w1[i];
    }
    if (tid < 64){
        s_b1[tid]=n_b1[tid]; s_b2[tid]=n_b2[tid];
        s_eb1[tid]=e_b1[tid]; s_vb1[tid]=v_b1[tid]; s_vw2[tid]=v_w2[tid];
    }
    __syncthreads();
    int lane = tid & 31, warp = tid >> 5;
    int j0 = 2*lane;
    int wpb = blockDim.x >> 5;
    float vb2 = v_b2[0];
    for (int n = blockIdx.x*wpb + warp; n < NN; n += gridDim.x*wpb){
        float h0 = g_h[n*H+j0],    h1 = g_h[n*H+j0+1];
        float m0 = g_magg[n*H+j0], m1 = g_magg[n*H+j0+1];
        float u0 = s_b1[j0], u1 = s_b1[j0+1];
        #pragma unroll
        for (int k=0;k<H;k++){
            float hk = __shfl_sync(0xffffffffu, (k&1)?h1:h0, k>>1);
            float mk = __shfl_sync(0xffffffffu, (k&1)?m1:m0, k>>1);
            float2 w1 = *(const float2*)&s_w1[k*H+j0];
            float2 w2 = *(const float2*)&s_w1[(H+k)*H+j0];
            u0 += hk*w1.x + mk*w2.x;
            u1 += hk*w1.y + mk*w2.y;
        }
        u0 = silu_f(u0); u1 = silu_f(u1);
        float a0 = s_b2[j0], a1 = s_b2[j0+1];
        #pragma unroll
        for (int k=0;k<H;k++){
            float uk = __shfl_sync(0xffffffffu, (k&1)?u1:u0, k>>1);
            float2 w = *(const float2*)&s_w2[k*H+j0];
            a0 += uk*w.x; a1 += uk*w.y;
        }
        float hn0 = 2.f*h0 + a0, hn1 = 2.f*h1 + a1;
        *(float2*)&g_h[n*H+j0] = make_float2(hn0, hn1);
        if (lane < 3){
            float dg = g_deg[n];
            float cm = g_cagg4[n*4+lane] / dg;
            float vi = g_v4[n*4+lane];
            float vn = vi + cm + g_vel[n]*vi;
            g_v4[n*4+lane] = vn;
            g_x4[n*4+lane] += vn;
        }
        if (do_pre){
            // next-layer A/B/vel from hn (register-resident)
            float A0 = s_eb1[j0], A1 = s_eb1[j0+1];
            float B0 = 0.f, B1 = 0.f;
            float t0 = s_vb1[j0], t1 = s_vb1[j0+1];
            #pragma unroll
            for (int k=0;k<H;k++){
                float hk = __shfl_sync(0xffffffffu, (k&1)?hn1:hn0, k>>1);
                float2 wa = *(const float2*)&s_ew[k*H+j0];
                float2 wb = *(const float2*)&s_ew[(H+k)*H+j0];
                float2 wv = *(const float2*)&s_vw[k*H+j0];
                A0 += hk*wa.x; A1 += hk*wa.y;
                B0 += hk*wb.x; B1 += hk*wb.y;
                t0 += hk*wv.x; t1 += hk*wv.y;
            }
            *(float2*)&g_A[n*H+j0]    = make_float2(A0,A1);
            *(float2*)&g_B[n*H+j0]    = make_float2(B0,B1);
            *(float2*)&g_magg[n*H+j0] = make_float2(0.f,0.f);
            float p = silu_f(t0)*s_vw2[j0] + silu_f(t1)*s_vw2[j0+1];
            #pragma unroll
            for (int o=16;o>0;o>>=1) p += __shfl_xor_sync(0xffffffffu, p, o);
            if (lane == 0){
                g_vel[n] = p + vb2;
                *(float4*)&g_cagg4[n*4] = make_float4(0.f,0.f,0.f,0.f);
            }
        }
    }
}

// ---------------- output: [x | h | v] ---------------------------------------------
__global__ void k_out(float* __restrict__ out){
    int i = blockIdx.x*blockDim.x + threadIdx.x;
    if (i < NN*3){
        int n = i/3, d = i - n*3;
        out[i] = g_x4[n*4+d];
    } else if (i < NN*3+NN*H){
        out[i] = g_h[i-NN*3];
    } else if (i < NN*(6+H)){
        int j = i - NN*3 - NN*H;
        int n = j/3, d = j - n*3;
        out[i] = g_v4[n*4+d];
    }
}

extern "C" void kernel_launch(void* const* d_in, const int* in_sizes, int n_in,
                              void* d_out, int out_size){
    const float* his  = (const float*)d_in[0];
    const float* x    = (const float*)d_in[1];
    const float* v    = (const float*)d_in[2];
    const float* edge_attr = (const float*)d_in[3];
    const int*   edges= (const int*)  d_in[4];
    const float* emb_w= (const float*)d_in[5];
    const float* emb_b= (const float*)d_in[6];
    const float* e_w1 = (const float*)d_in[7];
    const float* e_b1 = (const float*)d_in[8];
    const float* e_w2 = (const float*)d_in[9];
    const float* e_b2 = (const float*)d_in[10];
    const float* c_w1 = (const float*)d_in[11];
    const float* c_b1 = (const float*)d_in[12];
    const float* c_w2 = (const float*)d_in[13];
    const float* n_w1 = (const float*)d_in[14];
    const float* n_b1 = (const float*)d_in[15];
    const float* n_w2 = (const float*)d_in[16];
    const float* n_b2 = (const float*)d_in[17];
    const float* v_w1 = (const float*)d_in[18];
    const float* v_b1 = (const float*)d_in[19];
    const float* v_w2 = (const float*)d_in[20];
    const float* v_b2 = (const float*)d_in[21];

    const int PREVEL_SMEM = 12480*4;
    const int NODE_SMEM   = 24896*4;   // 99584 B
    const int EDGE_SMEM   = 18304*4;   // 73216 B
    cudaFuncSetAttribute(k_prevel, cudaFuncAttributeMaxDynamicSharedMemorySize, PREVEL_SMEM);
    cudaFuncSetAttribute(k_node,   cudaFuncAttributeMaxDynamicSharedMemorySize, NODE_SMEM);
    cudaFuncSetAttribute(k_edge,   cudaFuncAttributeMaxDynamicSharedMemorySize, EDGE_SMEM);

    k_init<<<(NN*H+255)/256, 256>>>(his, emb_w, emb_b, x, v);
    k_deg<<<(EE+255)/256, 256>>>(edges);
    k_scan<<<1, 1024>>>();
    k_fill<<<(EE+255)/256, 256>>>(edges, edge_attr);

    const int gn = 1184;
    const int gf = 296;    // fused node: 2 blocks/SM (99.6 KB smem)
    const int ge = 444;

    k_prevel<<<gn, 256, PREVEL_SMEM>>>(e_w1, e_b1, v_w1, v_b1, v_w2, v_b2);
    for (int l=0; l<3; l++){
        k_edge<<<ge, TTH, EDGE_SMEM>>>(e_w1, e_w2, e_b2, c_w1, c_b1, c_w2);
        k_node<<<gf, 256, NODE_SMEM>>>(n_w1, n_b1, n_w2, n_b2,
                                       e_w1, e_b1, v_w1, v_b1, v_w2, v_b2,
                                       (l < 2) ? 1 : 0);
    }
    k_out<<<(NN*(H+6)+255)/256, 256>>>((float*)d_out);
}

// round 9
// speedup vs baseline: 1.0556x; 1.0556x over previous
#include <cuda_runtime.h>

#define NN 50000
#define EE 1600000
#define H  64
#define TG  32      // edges per group-tile
#define NGB 4       // groups per block
#define TTH 256     // threads per edge block
#define RL3 32      // s_t row length
#define NTG (EE/TG) // 50000 group-tiles

typedef unsigned long long ull;

// ---------------- scratch (device globals; no allocation allowed) ----------------
__device__ float g_h[NN*H];
__device__ float g_A[NN*H];      // h@Wa + e_b1
__device__ float g_B[NN*H];      // h@Wb
__device__ float g_magg[NN*H];   // segment-summed messages
__device__ float g_cagg4[NN*4];  // segment-summed coord updates (padded)
__device__ float g_vel[NN];      // vel_scale
__device__ float g_deg[NN];      // clipped out-degree (float)
__device__ int   g_cnt[NN];      // raw out-degree
__device__ int   g_off[NN];      // fill cursors
__device__ float g_x4[NN*4];     // padded coords
__device__ float g_v4[NN*4];     // padded velocities
__device__ int   g_tile;         // dynamic tile cursor for k_edge
// r-sorted edge arrays
__device__ int    g_er[EE];
__device__ int    g_ec[EE];
__device__ float2 g_ea2[EE];

__device__ __forceinline__ float silu_f(float x){
    float th;
    asm("tanh.approx.f32 %0, %1;" : "=f"(th) : "f"(0.5f*x));
    return 0.5f*x*th + 0.5f*x;
}
__device__ __forceinline__ ull pack2(float x, float y){
    ull r; asm("mov.b64 %0, {%1,%2};" : "=l"(r) : "f"(x), "f"(y)); return r;
}
__device__ __forceinline__ float2 unpack2(ull p){
    float2 r; asm("mov.b64 {%0,%1}, %2;" : "=f"(r.x), "=f"(r.y) : "l"(p)); return r;
}
__device__ __forceinline__ void fma2(ull& d, ull a, ull b){
    asm("fma.rn.f32x2 %0, %1, %2, %0;" : "+l"(d) : "l"(a), "l"(b));
}
__device__ __forceinline__ void red4(float* p, float a, float b, float c, float d){
    asm volatile("red.global.add.v4.f32 [%0], {%1,%2,%3,%4};"
                 :: "l"(p), "f"(a), "f"(b), "f"(c), "f"(d) : "memory");
}
__device__ __forceinline__ void pf_l1(const float* p){
    asm volatile("prefetch.global.L1 [%0];" :: "l"(p));
}

// ---------------- init ------------------------------------------------------------
__global__ void k_init(const float* __restrict__ his, const float* __restrict__ emb_w,
                       const float* __restrict__ emb_b, const float* __restrict__ x,
                       const float* __restrict__ v){
    int idx = blockIdx.x*blockDim.x + threadIdx.x;
    if (idx < NN*H){
        int n = idx >> 6, j = idx & 63;
        float acc = emb_b[j];
        #pragma unroll
        for (int k=0;k<16;k++) acc += his[n*16+k]*emb_w[k*H+j];
        g_h[idx] = acc;
    }
    if (idx < NN){
        g_x4[idx*4+0]=x[idx*3+0]; g_x4[idx*4+1]=x[idx*3+1]; g_x4[idx*4+2]=x[idx*3+2]; g_x4[idx*4+3]=0.f;
        g_v4[idx*4+0]=v[idx*3+0]; g_v4[idx*4+1]=v[idx*3+1]; g_v4[idx*4+2]=v[idx*3+2]; g_v4[idx*4+3]=0.f;
        g_cnt[idx] = 0;
    }
}

__global__ void k_deg(const int* __restrict__ edges){
    int e = blockIdx.x*blockDim.x + threadIdx.x;
    if (e < EE) atomicAdd(&g_cnt[edges[e]], 1);
}

// single-block exclusive scan over g_cnt -> g_off; also g_deg = max(cnt,1)
__global__ void k_scan(){
    __shared__ int s_part[1024];
    int tid = threadIdx.x;
    const int CH = (NN + 1023)/1024;   // 49
    int base = tid*CH;
    int sum = 0;
    #pragma unroll 7
    for (int i=0;i<CH;i++){ int n=base+i; if(n<NN) sum += g_cnt[n]; }
    s_part[tid] = sum;
    __syncthreads();
    for (int off=1; off<1024; off<<=1){
        int t = (tid >= off) ? s_part[tid-off] : 0;
        __syncthreads();
        s_part[tid] += t;
        __syncthreads();
    }
    int run = s_part[tid] - sum;
    for (int i=0;i<CH;i++){
        int n = base+i;
        if (n < NN){
            int c = g_cnt[n];
            g_off[n] = run;
            g_deg[n] = (c > 0) ? (float)c : 1.0f;
            run += c;
        }
    }
}

__global__ void k_fill(const int* __restrict__ edges, const float* __restrict__ edge_attr){
    int e = blockIdx.x*blockDim.x + threadIdx.x;
    if (e < EE){
        int r = edges[e];
        int pos = atomicAdd(&g_off[r], 1);
        g_er[pos] = r;
        g_ec[pos] = edges[EE+e];
        g_ea2[pos] = ((const float2*)edge_attr)[e];
    }
}

// ------ per-layer node precompute: A,B, vel_scale; zero aggs; reset tile cursor ---
__global__ void k_prevel(const float* __restrict__ e_w1, const float* __restrict__ e_b1,
                         const float* __restrict__ v_w1, const float* __restrict__ v_b1,
                         const float* __restrict__ v_w2, const float* __restrict__ v_b2){
    extern __shared__ float sp[];
    float* s_ew  = sp;            // 128x64
    float* s_vw  = sp + 8192;     // 64x64
    float* s_eb1 = sp + 12288;
    float* s_vb1 = sp + 12352;
    float* s_vw2 = sp + 12416;
    int tid = threadIdx.x;
    if (blockIdx.x == 0 && tid == 0) g_tile = 0;
    for (int i=tid; i<8192; i+=blockDim.x) s_ew[i] = e_w1[i];
    for (int i=tid; i<4096; i+=blockDim.x) s_vw[i] = v_w1[i];
    if (tid < 64){ s_eb1[tid]=e_b1[tid]; s_vb1[tid]=v_b1[tid]; s_vw2[tid]=v_w2[tid]; }
    __syncthreads();
    int lane = tid & 31, warp = tid >> 5;
    int j0 = 2*lane;
    int wpb = blockDim.x >> 5;
    float vb2 = v_b2[0];
    for (int n = blockIdx.x*wpb + warp; n < NN; n += gridDim.x*wpb){
        float h0 = g_h[n*H+j0], h1 = g_h[n*H+j0+1];
        float a0 = s_eb1[j0], a1 = s_eb1[j0+1];
        float b0 = 0.f, b1 = 0.f;
        float t0 = s_vb1[j0], t1 = s_vb1[j0+1];
        #pragma unroll
        for (int k=0;k<H;k++){
            float hk = __shfl_sync(0xffffffffu, (k&1)?h1:h0, k>>1);
            float2 wa = *(const float2*)&s_ew[k*H+j0];
            float2 wb = *(const float2*)&s_ew[(H+k)*H+j0];
            float2 wv = *(const float2*)&s_vw[k*H+j0];
            a0 += hk*wa.x; a1 += hk*wa.y;
            b0 += hk*wb.x; b1 += hk*wb.y;
            t0 += hk*wv.x; t1 += hk*wv.y;
        }
        *(float2*)&g_A[n*H+j0]    = make_float2(a0,a1);
        *(float2*)&g_B[n*H+j0]    = make_float2(b0,b1);
        *(float2*)&g_magg[n*H+j0] = make_float2(0.f,0.f);
        float p = silu_f(t0)*s_vw2[j0] + silu_f(t1)*s_vw2[j0+1];
        #pragma unroll
        for (int o=16;o>0;o>>=1) p += __shfl_xor_sync(0xffffffffu, p, o);
        if (lane == 0){
            g_vel[n] = p + vb2;
            *(float4*)&g_cagg4[n*4] = make_float4(0.f,0.f,0.f,0.f);
        }
    }
}

// ------- edge kernel: 4x64-thread groups, dynamic tile stealing -------------------
__global__ void __launch_bounds__(TTH, 3)
k_edge(const float* __restrict__ e_w1, const float* __restrict__ e_w2,
       const float* __restrict__ e_b2, const float* __restrict__ c_w1,
       const float* __restrict__ c_b1, const float* __restrict__ c_w2){
    extern __shared__ float sm[];
    float* s_w2  = sm;              // 4096 (block-shared, read-only)
    float* s_c1  = sm + 4096;       // 4096
    float* s_wr  = sm + 8192;       // 64
    float* s_we0 = sm + 8256;
    float* s_we1 = sm + 8320;
    float* s_eb2 = sm + 8384;
    float* s_cb1 = sm + 8448;
    float* s_cw2 = sm + 8512;       // .. 8576
    int tid = threadIdx.x;
    int g    = tid >> 6;            // group 0..3
    int gtid = tid & 63;
    float* gb    = sm + 8576 + g*2464;
    float* s_t   = gb;              // 64*RL3 = 2048
    float* s_gp  = gb + 2048;       // 8*32 = 256
    float* s_dx  = gb + 2304;       // 32
    float* s_dy  = gb + 2336;
    float* s_dz  = gb + 2368;
    int*   s_r   = (int*)(gb + 2400);   // 32
    int*   s_tl  = (int*)(gb + 2432);   // tile broadcast slot
    // total: 8576 + 4*2464 = 18432 floats = 73728 B

    for (int i=tid; i<4096; i+=TTH){ s_w2[i] = e_w2[i]; s_c1[i] = c_w1[i]; }
    if (tid < 64){
        s_wr [tid] = e_w1[128*H+tid];
        s_we0[tid] = e_w1[129*H+tid];
        s_we1[tid] = e_w1[130*H+tid];
        s_eb2[tid] = e_b2[tid];
        s_cb1[tid] = c_b1[tid];
        s_cw2[tid] = c_w2[tid];
    }
    if (gtid == 0) s_tl[0] = atomicAdd(&g_tile, 1);
    __syncthreads();

    int el = gtid & 31, hf = gtid >> 5;   // P1 mapping (2 threads/edge)
    int eg = gtid & 7,  og = gtid >> 3;   // GEMM mapping: 4 edges x 8 outputs
    int bar = g + 1;

    int tile = s_tl[0];
    while (tile < NTG){
        // ---- P1: gather + first-layer pre + silu -> s_t[k][e] ----
        {
            int e = tile*TG + el;
            int r = g_er[e], c = g_ec[e];
            float4 xr = *(const float4*)&g_x4[r*4];
            float4 xc = *(const float4*)&g_x4[c*4];
            float dx = xr.x-xc.x, dy = xr.y-xc.y, dz = xr.z-xc.z;
            float radial = dx*dx + dy*dy + dz*dz;
            float2 ea = g_ea2[e];
            const float4* Ap = (const float4*)(g_A + r*H + hf*32);
            const float4* Bp = (const float4*)(g_B + c*H + hf*32);
            int kb = hf*32;
            #pragma unroll
            for (int q=0;q<8;q++){
                float4 a = Ap[q], b = Bp[q];
                int k = kb + 4*q;
                float4 w1 = *(const float4*)&s_wr [k];
                float4 w2 = *(const float4*)&s_we0[k];
                float4 w3 = *(const float4*)&s_we1[k];
                s_t[(k+0)*RL3+el] = silu_f(a.x + b.x + radial*w1.x + ea.x*w2.x + ea.y*w3.x);
                s_t[(k+1)*RL3+el] = silu_f(a.y + b.y + radial*w1.y + ea.x*w2.y + ea.y*w3.y);
                s_t[(k+2)*RL3+el] = silu_f(a.z + b.z + radial*w1.z + ea.x*w2.z + ea.y*w3.z);
                s_t[(k+3)*RL3+el] = silu_f(a.w + b.w + radial*w1.w + ea.x*w2.w + ea.y*w3.w);
            }
            if (!hf){ s_r[el]=r; s_dx[el]=dx; s_dy[el]=dy; s_dz[el]=dz; }
        }
        asm volatile("bar.sync %0, 64;" :: "r"(bar) : "memory");

        // ---- P2: GEMM1  M[e][j] = sum_k s_t[k][e] * w2[k][j] ----
        ull acc[16];
        {
            ull b0 = *(const ull*)&s_eb2[og*8+0];
            ull b1 = *(const ull*)&s_eb2[og*8+2];
            ull b2 = *(const ull*)&s_eb2[og*8+4];
            ull b3 = *(const ull*)&s_eb2[og*8+6];
            #pragma unroll
            for (int e4=0;e4<4;e4++){ acc[e4*4]=b0; acc[e4*4+1]=b1; acc[e4*4+2]=b2; acc[e4*4+3]=b3; }
            const float* tp = s_t + eg*4;
            const float* wk = s_w2 + og*8;
            #pragma unroll 8
            for (int k=0;k<64;k++){
                float4 tv = *(const float4*)(tp + k*RL3);
                ulonglong2 wa = *(const ulonglong2*)(wk + k*64);
                ulonglong2 wb = *(const ulonglong2*)(wk + k*64 + 4);
                ull t0 = pack2(tv.x,tv.x), t1 = pack2(tv.y,tv.y);
                ull t2 = pack2(tv.z,tv.z), t3 = pack2(tv.w,tv.w);
                fma2(acc[0],  t0, wa.x); fma2(acc[1],  t0, wa.y); fma2(acc[2],  t0, wb.x); fma2(acc[3],  t0, wb.y);
                fma2(acc[4],  t1, wa.x); fma2(acc[5],  t1, wa.y); fma2(acc[6],  t1, wb.x); fma2(acc[7],  t1, wb.y);
                fma2(acc[8],  t2, wa.x); fma2(acc[9],  t2, wa.y); fma2(acc[10], t2, wb.x); fma2(acc[11], t2, wb.y);
                fma2(acc[12], t3, wa.x); fma2(acc[13], t3, wa.y); fma2(acc[14], t3, wb.x); fma2(acc[15], t3, wb.y);
            }
        }
        asm volatile("bar.sync %0, 64;" :: "r"(bar) : "memory");

        // ---- P3: silu(M), store ms -> s_t[j][e], run-aggregated scatter to m_agg -
        {
            float ms[4][8];
            #pragma unroll
            for (int e4=0;e4<4;e4++){
                #pragma unroll
                for (int jp=0;jp<4;jp++){
                    float2 f = unpack2(acc[e4*4+jp]);
                    ms[e4][2*jp]   = silu_f(f.x);
                    ms[e4][2*jp+1] = silu_f(f.y);
                }
            }
            #pragma unroll
            for (int j=0;j<8;j++){
                *(float4*)&s_t[(og*8+j)*RL3 + eg*4] =
                    make_float4(ms[0][j], ms[1][j], ms[2][j], ms[3][j]);
            }
            int rr[4] = {s_r[eg*4+0], s_r[eg*4+1], s_r[eg*4+2], s_r[eg*4+3]};
            int rh = 0;
            #pragma unroll
            for (int e4=1;e4<4;e4++){
                if (rr[e4] == rr[rh]){
                    #pragma unroll
                    for (int j=0;j<8;j++) ms[rh][j] += ms[e4][j];
                } else {
                    float* mp = &g_magg[rr[rh]*H + og*8];
                    red4(mp,   ms[rh][0], ms[rh][1], ms[rh][2], ms[rh][3]);
                    red4(mp+4, ms[rh][4], ms[rh][5], ms[rh][6], ms[rh][7]);
                    rh = e4;
                }
            }
            float* mp = &g_magg[rr[rh]*H + og*8];
            red4(mp,   ms[rh][0], ms[rh][1], ms[rh][2], ms[rh][3]);
            red4(mp+4, ms[rh][4], ms[rh][5], ms[rh][6], ms[rh][7]);
        }
        asm volatile("bar.sync %0, 64;" :: "r"(bar) : "memory");

        // ---- P4: GEMM2  U[e][j] = sum_k ms[k][e] * c1[k][j]; partial g ----
        {
            ull b0 = *(const ull*)&s_cb1[og*8+0];
            ull b1 = *(const ull*)&s_cb1[og*8+2];
            ull b2 = *(const ull*)&s_cb1[og*8+4];
            ull b3 = *(const ull*)&s_cb1[og*8+6];
            #pragma unroll
            for (int e4=0;e4<4;e4++){ acc[e4*4]=b0; acc[e4*4+1]=b1; acc[e4*4+2]=b2; acc[e4*4+3]=b3; }
            const float* tp = s_t + eg*4;
            const float* wk = s_c1 + og*8;
            #pragma unroll 8
            for (int k=0;k<64;k++){
                float4 tv = *(const float4*)(tp + k*RL3);
                ulonglong2 wa = *(const ulonglong2*)(wk + k*64);
                ulonglong2 wb = *(const ulonglong2*)(wk + k*64 + 4);
                ull t0 = pack2(tv.x,tv.x), t1 = pack2(tv.y,tv.y);
                ull t2 = pack2(tv.z,tv.z), t3 = pack2(tv.w,tv.w);
                fma2(acc[0],  t0, wa.x); fma2(acc[1],  t0, wa.y); fma2(acc[2],  t0, wb.x); fma2(acc[3],  t0, wb.y);
                fma2(acc[4],  t1, wa.x); fma2(acc[5],  t1, wa.y); fma2(acc[6],  t1, wb.x); fma2(acc[7],  t1, wb.y);
                fma2(acc[8],  t2, wa.x); fma2(acc[9],  t2, wa.y); fma2(acc[10], t2, wb.x); fma2(acc[11], t2, wb.y);
                fma2(acc[12], t3, wa.x); fma2(acc[13], t3, wa.y); fma2(acc[14], t3, wb.x); fma2(acc[15], t3, wb.y);
            }
            float gp[4];
            #pragma unroll
            for (int e4=0;e4<4;e4++){
                float s = 0.f;
                #pragma unroll
                for (int jp=0;jp<4;jp++){
                    float2 f = unpack2(acc[e4*4+jp]);
                    s += silu_f(f.x)*s_cw2[og*8+2*jp] + silu_f(f.y)*s_cw2[og*8+2*jp+1];
                }
                gp[e4] = s;
            }
            *(float4*)&s_gp[og*32 + eg*4] = make_float4(gp[0],gp[1],gp[2],gp[3]);
        }
        asm volatile("bar.sync %0, 64;" :: "r"(bar) : "memory");

        // ---- P5: reduce g across out-groups; segmented coord scatter; steal next -
        if (gtid < 32){
            float gg = 0.f;
            #pragma unroll
            for (int o=0;o<8;o++) gg += s_gp[o*32 + gtid];
            int r = s_r[gtid];
            float cx = s_dx[gtid]*gg, cy = s_dy[gtid]*gg, cz = s_dz[gtid]*gg;
            unsigned fm = 0xffffffffu;
            #pragma unroll
            for (int off=1; off<32; off<<=1){
                int ro   = __shfl_down_sync(fm, r,  off);
                float xo = __shfl_down_sync(fm, cx, off);
                float yo = __shfl_down_sync(fm, cy, off);
                float zo = __shfl_down_sync(fm, cz, off);
                if (gtid + off < 32 && ro == r){ cx += xo; cy += yo; cz += zo; }
            }
            int rp = __shfl_up_sync(fm, r, 1);
            if (gtid == 0 || rp != r)
                red4(&g_cagg4[r*4], cx, cy, cz, 0.f);
            if (gtid == 0) s_tl[0] = atomicAdd(&g_tile, 1);
        }
        asm volatile("bar.sync %0, 64;" :: "r"(bar) : "memory");
        tile = s_tl[0];
    }
}

// -------- fused node MLP + state update ------------------------------------------
__global__ void k_node(const float* __restrict__ n_w1, const float* __restrict__ n_b1,
                       const float* __restrict__ n_w2, const float* __restrict__ n_b2){
    extern __shared__ float sn[];
    float* s_w1 = sn;           // 128x64
    float* s_w2 = sn + 8192;    // 64x64
    float* s_b1 = sn + 12288;
    float* s_b2 = sn + 12352;
    int tid = threadIdx.x;
    for (int i=tid; i<8192; i+=blockDim.x) s_w1[i] = n_w1[i];
    for (int i=tid; i<4096; i+=blockDim.x) s_w2[i] = n_w2[i];
    if (tid < 64){ s_b1[tid]=n_b1[tid]; s_b2[tid]=n_b2[tid]; }
    __syncthreads();
    int lane = tid & 31, warp = tid >> 5;
    int j0 = 2*lane;
    int wpb = blockDim.x >> 5;
    for (int n = blockIdx.x*wpb + warp; n < NN; n += gridDim.x*wpb){
        float h0 = g_h[n*H+j0],    h1 = g_h[n*H+j0+1];
        float m0 = g_magg[n*H+j0], m1 = g_magg[n*H+j0+1];
        float u0 = s_b1[j0], u1 = s_b1[j0+1];
        #pragma unroll
        for (int k=0;k<H;k++){
            float hk = __shfl_sync(0xffffffffu, (k&1)?h1:h0, k>>1);
            float mk = __shfl_sync(0xffffffffu, (k&1)?m1:m0, k>>1);
            float2 w1 = *(const float2*)&s_w1[k*H+j0];
            float2 w2 = *(const float2*)&s_w1[(H+k)*H+j0];
            u0 += hk*w1.x + mk*w2.x;
            u1 += hk*w1.y + mk*w2.y;
        }
        u0 = silu_f(u0); u1 = silu_f(u1);
        float a0 = s_b2[j0], a1 = s_b2[j0+1];
        #pragma unroll
        for (int k=0;k<H;k++){
            float uk = __shfl_sync(0xffffffffu, (k&1)?u1:u0, k>>1);
            float2 w = *(const float2*)&s_w2[k*H+j0];
            a0 += uk*w.x; a1 += uk*w.y;
        }
        *(float2*)&g_h[n*H+j0] = make_float2(2.f*h0 + a0, 2.f*h1 + a1);
        if (lane < 3){
            float dg = g_deg[n];
            float cm = g_cagg4[n*4+lane] / dg;
            float vi = g_v4[n*4+lane];
            float vn = vi + cm + g_vel[n]*vi;
            g_v4[n*4+lane] = vn;
            g_x4[n*4+lane] += vn;
        }
    }
}

// ---------------- output: [x | h | v] ---------------------------------------------
__global__ void k_out(float* __restrict__ out){
    int i = blockIdx.x*blockDim.x + threadIdx.x;
    if (i < NN*3){
        int n = i/3, d = i - n*3;
        out[i] = g_x4[n*4+d];
    } else if (i < NN*3+NN*H){
        out[i] = g_h[i-NN*3];
    } else if (i < NN*(6+H)){
        int j = i - NN*3 - NN*H;
        int n = j/3, d = j - n*3;
        out[i] = g_v4[n*4+d];
    }
}

extern "C" void kernel_launch(void* const* d_in, const int* in_sizes, int n_in,
                              void* d_out, int out_size){
    const float* his  = (const float*)d_in[0];
    const float* x    = (const float*)d_in[1];
    const float* v    = (const float*)d_in[2];
    const float* edge_attr = (const float*)d_in[3];
    const int*   edges= (const int*)  d_in[4];
    const float* emb_w= (const float*)d_in[5];
    const float* emb_b= (const float*)d_in[6];
    const float* e_w1 = (const float*)d_in[7];
    const float* e_b1 = (const float*)d_in[8];
    const float* e_w2 = (const float*)d_in[9];
    const float* e_b2 = (const float*)d_in[10];
    const float* c_w1 = (const float*)d_in[11];
    const float* c_b1 = (const float*)d_in[12];
    const float* c_w2 = (const float*)d_in[13];
    const float* n_w1 = (const float*)d_in[14];
    const float* n_b1 = (const float*)d_in[15];
    const float* n_w2 = (const float*)d_in[16];
    const float* n_b2 = (const float*)d_in[17];
    const float* v_w1 = (const float*)d_in[18];
    const float* v_b1 = (const float*)d_in[19];
    const float* v_w2 = (const float*)d_in[20];
    const float* v_b2 = (const float*)d_in[21];

    const int PREVEL_SMEM = 12480*4;
    const int NODE_SMEM   = 12416*4;
    const int EDGE_SMEM   = 18432*4;   // 73728 B
    cudaFuncSetAttribute(k_prevel, cudaFuncAttributeMaxDynamicSharedMemorySize, PREVEL_SMEM);
    cudaFuncSetAttribute(k_node,   cudaFuncAttributeMaxDynamicSharedMemorySize, NODE_SMEM);
    cudaFuncSetAttribute(k_edge,   cudaFuncAttributeMaxDynamicSharedMemorySize, EDGE_SMEM);

    k_init<<<(NN*H+255)/256, 256>>>(his, emb_w, emb_b, x, v);
    k_deg<<<(EE+255)/256, 256>>>(edges);
    k_scan<<<1, 1024>>>();
    k_fill<<<(EE+255)/256, 256>>>(edges, edge_attr);

    const int gn = 444;    // node kernels: better weight-staging amortization
    const int ge = 444;    // edge kernel: 3 blocks/SM, dynamic stealing

    for (int l=0; l<3; l++){
        k_prevel<<<gn, 256, PREVEL_SMEM>>>(e_w1, e_b1, v_w1, v_b1, v_w2, v_b2);
        k_edge<<<ge, TTH, EDGE_SMEM>>>(e_w1, e_w2, e_b2, c_w1, c_b1, c_w2);
        k_node<<<gn, 256, NODE_SMEM>>>(n_w1, n_b1, n_w2, n_b2);
    }
    k_out<<<(NN*(H+6)+255)/256, 256>>>((float*)d_out);
}

// round 12
// speedup vs baseline: 1.0653x; 1.0091x over previous
#include <cuda_runtime.h>

#define NN 50000
#define EE 1600000
#define H  64
#define STEAL (EE/32)   // 50000 steal units of 32 edges (2 x 16-edge subtiles)

typedef unsigned long long ull;

// ---------------- scratch (device globals; no allocation allowed) ----------------
__device__ float g_h[NN*H];
__device__ float g_A[NN*H];      // h@Wa + e_b1
__device__ float g_B[NN*H];      // h@Wb
__device__ float g_magg[NN*H];   // segment-summed messages
__device__ float g_cagg4[NN*4];  // segment-summed coord updates (padded)
__device__ float g_vel[NN];      // vel_scale
__device__ float g_deg[NN];      // clipped out-degree (float)
__device__ int   g_cnt[NN];      // raw out-degree
__device__ int   g_off[NN];      // fill cursors
__device__ float g_x4[NN*4];     // padded coords
__device__ float g_v4[NN*4];     // padded velocities
__device__ int   g_tile;         // dynamic steal cursor
// r-sorted edge arrays
__device__ int    g_er[EE];
__device__ int    g_ec[EE];
__device__ float2 g_ea2[EE];

__device__ __forceinline__ float silu_f(float x){
    float th;
    asm("tanh.approx.f32 %0, %1;" : "=f"(th) : "f"(0.5f*x));
    return 0.5f*x*th + 0.5f*x;
}
__device__ __forceinline__ ull pack2(float x, float y){
    ull r; asm("mov.b64 %0, {%1,%2};" : "=l"(r) : "f"(x), "f"(y)); return r;
}
__device__ __forceinline__ float2 unpack2(ull p){
    float2 r; asm("mov.b64 {%0,%1}, %2;" : "=f"(r.x), "=f"(r.y) : "l"(p)); return r;
}
__device__ __forceinline__ void fma2(ull& d, ull a, ull b){
    asm("fma.rn.f32x2 %0, %1, %2, %0;" : "+l"(d) : "l"(a), "l"(b));
}
__device__ __forceinline__ void red4(float* p, float a, float b, float c, float d){
    asm volatile("red.global.add.v4.f32 [%0], {%1,%2,%3,%4};"
                 :: "l"(p), "f"(a), "f"(b), "f"(c), "f"(d) : "memory");
}

// ---------------- init ------------------------------------------------------------
__global__ void k_init(const float* __restrict__ his, const float* __restrict__ emb_w,
                       const float* __restrict__ emb_b, const float* __restrict__ x,
                       const float* __restrict__ v){
    int idx = blockIdx.x*blockDim.x + threadIdx.x;
    if (idx < NN*H){
        int n = idx >> 6, j = idx & 63;
        float acc = emb_b[j];
        #pragma unroll
        for (int k=0;k<16;k++) acc += his[n*16+k]*emb_w[k*H+j];
        g_h[idx] = acc;
    }
    if (idx < NN){
        g_x4[idx*4+0]=x[idx*3+0]; g_x4[idx*4+1]=x[idx*3+1]; g_x4[idx*4+2]=x[idx*3+2]; g_x4[idx*4+3]=0.f;
        g_v4[idx*4+0]=v[idx*3+0]; g_v4[idx*4+1]=v[idx*3+1]; g_v4[idx*4+2]=v[idx*3+2]; g_v4[idx*4+3]=0.f;
        g_cnt[idx] = 0;
    }
}

__global__ void k_deg(const int* __restrict__ edges){
    int e = blockIdx.x*blockDim.x + threadIdx.x;
    if (e < EE) atomicAdd(&g_cnt[edges[e]], 1);
}

// single-block exclusive scan over g_cnt -> g_off; also g_deg = max(cnt,1)
__global__ void k_scan(){
    __shared__ int s_part[1024];
    int tid = threadIdx.x;
    const int CH = (NN + 1023)/1024;
    int base = tid*CH;
    int sum = 0;
    #pragma unroll 7
    for (int i=0;i<CH;i++){ int n=base+i; if(n<NN) sum += g_cnt[n]; }
    s_part[tid] = sum;
    __syncthreads();
    for (int off=1; off<1024; off<<=1){
        int t = (tid >= off) ? s_part[tid-off] : 0;
        __syncthreads();
        s_part[tid] += t;
        __syncthreads();
    }
    int run = s_part[tid] - sum;
    for (int i=0;i<CH;i++){
        int n = base+i;
        if (n < NN){
            int c = g_cnt[n];
            g_off[n] = run;
            g_deg[n] = (c > 0) ? (float)c : 1.0f;
            run += c;
        }
    }
}

__global__ void k_fill(const int* __restrict__ edges, const float* __restrict__ edge_attr){
    int e = blockIdx.x*blockDim.x + threadIdx.x;
    if (e < EE){
        int r = edges[e];
        int pos = atomicAdd(&g_off[r], 1);
        g_er[pos] = r;
        g_ec[pos] = edges[EE+e];
        g_ea2[pos] = ((const float2*)edge_attr)[e];
    }
}

// ------ per-layer node precompute: A,B, vel_scale; zero aggs; reset cursor --------
__global__ void k_prevel(const float* __restrict__ e_w1, const float* __restrict__ e_b1,
                         const float* __restrict__ v_w1, const float* __restrict__ v_b1,
                         const float* __restrict__ v_w2, const float* __restrict__ v_b2){
    extern __shared__ float sp[];
    float* s_ew  = sp;
    float* s_vw  = sp + 8192;
    float* s_eb1 = sp + 12288;
    float* s_vb1 = sp + 12352;
    float* s_vw2 = sp + 12416;
    int tid = threadIdx.x;
    if (blockIdx.x == 0 && tid == 0) g_tile = 0;
    for (int i=tid; i<8192; i+=blockDim.x) s_ew[i] = e_w1[i];
    for (int i=tid; i<4096; i+=blockDim.x) s_vw[i] = v_w1[i];
    if (tid < 64){ s_eb1[tid]=e_b1[tid]; s_vb1[tid]=v_b1[tid]; s_vw2[tid]=v_w2[tid]; }
    __syncthreads();
    int lane = tid & 31, warp = tid >> 5;
    int j0 = 2*lane;
    int wpb = blockDim.x >> 5;
    float vb2 = v_b2[0];
    for (int n = blockIdx.x*wpb + warp; n < NN; n += gridDim.x*wpb){
        float h0 = g_h[n*H+j0], h1 = g_h[n*H+j0+1];
        float a0 = s_eb1[j0], a1 = s_eb1[j0+1];
        float b0 = 0.f, b1 = 0.f;
        float t0 = s_vb1[j0], t1 = s_vb1[j0+1];
        #pragma unroll
        for (int k=0;k<H;k++){
            float hk = __shfl_sync(0xffffffffu, (k&1)?h1:h0, k>>1);
            float2 wa = *(const float2*)&s_ew[k*H+j0];
            float2 wb = *(const float2*)&s_ew[(H+k)*H+j0];
            float2 wv = *(const float2*)&s_vw[k*H+j0];
            a0 += hk*wa.x; a1 += hk*wa.y;
            b0 += hk*wb.x; b1 += hk*wb.y;
            t0 += hk*wv.x; t1 += hk*wv.y;
        }
        *(float2*)&g_A[n*H+j0]    = make_float2(a0,a1);
        *(float2*)&g_B[n*H+j0]    = make_float2(b0,b1);
        *(float2*)&g_magg[n*H+j0] = make_float2(0.f,0.f);
        float p = silu_f(t0)*s_vw2[j0] + silu_f(t1)*s_vw2[j0+1];
        #pragma unroll
        for (int o=16;o>0;o>>=1) p += __shfl_xor_sync(0xffffffffu, p, o);
        if (lane == 0){
            g_vel[n] = p + vb2;
            *(float4*)&g_cagg4[n*4] = make_float4(0.f,0.f,0.f,0.f);
        }
    }
}

// ------- edge kernel: warp-autonomous 16-edge subtiles, no cross-warp barriers ----
__global__ void __launch_bounds__(256, 3)
k_edge(const float* __restrict__ e_w1, const float* __restrict__ e_w2,
       const float* __restrict__ e_b2, const float* __restrict__ c_w1,
       const float* __restrict__ c_b1, const float* __restrict__ c_w2){
    extern __shared__ float sm[];
    float* s_w2  = sm;              // 4096 (block-shared, read-only)
    float* s_c1  = sm + 4096;       // 4096
    float* s_wr  = sm + 8192;       // 64
    float* s_we0 = sm + 8256;
    float* s_we1 = sm + 8320;
    float* s_eb2 = sm + 8384;
    float* s_cb1 = sm + 8448;
    float* s_cw2 = sm + 8512;       // .. 8576
    int tid  = threadIdx.x;
    int wid  = tid >> 5, lane = tid & 31;
    float* wbp  = sm + 8576 + wid*1088;   // per-warp region (1088 floats)
    float* s_t  = wbp;                    // 64 x 16
    int*   s_r  = (int*)(wbp + 1024);     // 16
    float* s_dx = wbp + 1040;             // 16
    float* s_dy = wbp + 1056;
    float* s_dz = wbp + 1072;
    // total smem: 8576 + 8*1088 = 17280 floats = 69120 B

    for (int i=tid; i<4096; i+=256){ s_w2[i] = e_w2[i]; s_c1[i] = c_w1[i]; }
    if (tid < 64){
        s_wr [tid] = e_w1[128*H+tid];
        s_we0[tid] = e_w1[129*H+tid];
        s_we1[tid] = e_w1[130*H+tid];
        s_eb2[tid] = e_b2[tid];
        s_cb1[tid] = c_b1[tid];
        s_cw2[tid] = c_w2[tid];
    }
    __syncthreads();

    const unsigned FM = 0xffffffffu;
    int el = lane & 15, hf = lane >> 4;   // P1: 2 lanes/edge
    int eg = lane & 3,  og = lane >> 2;   // GEMMs: 4 edges x 8 outputs per lane

    int base = 0;
    if (lane == 0) base = atomicAdd(&g_tile, 1);
    base = __shfl_sync(FM, base, 0);

    while (base < STEAL){
        #pragma unroll 1
        for (int sub=0; sub<2; sub++){
            // ---- P1: gather + first-layer pre + silu -> s_t[k][e] ----
            {
                int e = base*32 + sub*16 + el;
                int r = g_er[e], c = g_ec[e];
                float4 xr = *(const float4*)&g_x4[r*4];
                float4 xc = *(const float4*)&g_x4[c*4];
                float dx = xr.x-xc.x, dy = xr.y-xc.y, dz = xr.z-xc.z;
                float radial = dx*dx + dy*dy + dz*dz;
                float2 ea = g_ea2[e];
                const float4* Ap = (const float4*)(g_A + r*H + hf*32);
                const float4* Bp = (const float4*)(g_B + c*H + hf*32);
                int kb = hf*32;
                #pragma unroll
                for (int q=0;q<8;q++){
                    float4 av = Ap[q], bv = Bp[q];
                    int k = kb + 4*q;
                    float4 w1 = *(const float4*)&s_wr [k];
                    float4 w2 = *(const float4*)&s_we0[k];
                    float4 w3 = *(const float4*)&s_we1[k];
                    s_t[(k+0)*16+el] = silu_f(av.x + bv.x + radial*w1.x + ea.x*w2.x + ea.y*w3.x);
                    s_t[(k+1)*16+el] = silu_f(av.y + bv.y + radial*w1.y + ea.x*w2.y + ea.y*w3.y);
                    s_t[(k+2)*16+el] = silu_f(av.z + bv.z + radial*w1.z + ea.x*w2.z + ea.y*w3.z);
                    s_t[(k+3)*16+el] = silu_f(av.w + bv.w + radial*w1.w + ea.x*w2.w + ea.y*w3.w);
                }
                if (!hf){ s_r[el]=r; s_dx[el]=dx; s_dy[el]=dy; s_dz[el]=dz; }
            }
            __syncwarp();

            // ---- P2: GEMM1  M[e][j] = sum_k t[k][e] * w2[k][j] ----
            ull acc[16];
            {
                ull b0 = *(const ull*)&s_eb2[og*8+0];
                ull b1 = *(const ull*)&s_eb2[og*8+2];
                ull b2 = *(const ull*)&s_eb2[og*8+4];
                ull b3 = *(const ull*)&s_eb2[og*8+6];
                #pragma unroll
                for (int e4=0;e4<4;e4++){ acc[e4*4]=b0; acc[e4*4+1]=b1; acc[e4*4+2]=b2; acc[e4*4+3]=b3; }
                const float* tp = s_t + eg*4;
                const float* wk = s_w2 + og*8;
                #pragma unroll 8
                for (int k=0;k<64;k++){
                    float4 tv = *(const float4*)(tp + k*16);
                    ulonglong2 wa = *(const ulonglong2*)(wk + k*64);
                    ulonglong2 wb = *(const ulonglong2*)(wk + k*64 + 4);
                    ull t0 = pack2(tv.x,tv.x), t1 = pack2(tv.y,tv.y);
                    ull t2 = pack2(tv.z,tv.z), t3 = pack2(tv.w,tv.w);
                    fma2(acc[0],  t0, wa.x); fma2(acc[1],  t0, wa.y); fma2(acc[2],  t0, wb.x); fma2(acc[3],  t0, wb.y);
                    fma2(acc[4],  t1, wa.x); fma2(acc[5],  t1, wa.y); fma2(acc[6],  t1, wb.x); fma2(acc[7],  t1, wb.y);
                    fma2(acc[8],  t2, wa.x); fma2(acc[9],  t2, wa.y); fma2(acc[10], t2, wb.x); fma2(acc[11], t2, wb.y);
                    fma2(acc[12], t3, wa.x); fma2(acc[13], t3, wa.y); fma2(acc[14], t3, wb.x); fma2(acc[15], t3, wb.y);
                }
            }
            __syncwarp();   // all P2 reads of s_t done before P3 overwrites

            // ---- P3: silu(M), store ms -> s_t[j][e], run-agg scatter to m_agg ----
            {
                float ms[4][8];
                #pragma unroll
                for (int e4=0;e4<4;e4++){
                    #pragma unroll
                    for (int jp=0;jp<4;jp++){
                        float2 f = unpack2(acc[e4*4+jp]);
                        ms[e4][2*jp]   = silu_f(f.x);
                        ms[e4][2*jp+1] = silu_f(f.y);
                    }
                }
                #pragma unroll
                for (int j=0;j<8;j++){
                    *(float4*)&s_t[(og*8+j)*16 + eg*4] =
                        make_float4(ms[0][j], ms[1][j], ms[2][j], ms[3][j]);
                }
                int rr[4] = {s_r[eg*4+0], s_r[eg*4+1], s_r[eg*4+2], s_r[eg*4+3]};
                int rh = 0;
                #pragma unroll
                for (int e4=1;e4<4;e4++){
                    if (rr[e4] == rr[rh]){
                        #pragma unroll
                        for (int j=0;j<8;j++) ms[rh][j] += ms[e4][j];
                    } else {
                        float* mp = &g_magg[rr[rh]*H + og*8];
                        red4(mp,   ms[rh][0], ms[rh][1], ms[rh][2], ms[rh][3]);
                        red4(mp+4, ms[rh][4], ms[rh][5], ms[rh][6], ms[rh][7]);
                        rh = e4;
                    }
                }
                float* mp = &g_magg[rr[rh]*H + og*8];
                red4(mp,   ms[rh][0], ms[rh][1], ms[rh][2], ms[rh][3]);
                red4(mp+4, ms[rh][4], ms[rh][5], ms[rh][6], ms[rh][7]);
            }
            __syncwarp();

            // ---- P4: GEMM2 + g partial; shfl-reduce over og; coord scatter ----
            {
                ull b0 = *(const ull*)&s_cb1[og*8+0];
                ull b1 = *(const ull*)&s_cb1[og*8+2];
                ull b2 = *(const ull*)&s_cb1[og*8+4];
                ull b3 = *(const ull*)&s_cb1[og*8+6];
                #pragma unroll
                for (int e4=0;e4<4;e4++){ acc[e4*4]=b0; acc[e4*4+1]=b1; acc[e4*4+2]=b2; acc[e4*4+3]=b3; }
                const float* tp = s_t + eg*4;
                const float* wk = s_c1 + og*8;
                #pragma unroll 8
                for (int k=0;k<64;k++){
                    float4 tv = *(const float4*)(tp + k*16);
                    ulonglong2 wa = *(const ulonglong2*)(wk + k*64);
                    ulonglong2 wb = *(const ulonglong2*)(wk + k*64 + 4);
                    ull t0 = pack2(tv.x,tv.x), t1 = pack2(tv.y,tv.y);
                    ull t2 = pack2(tv.z,tv.z), t3 = pack2(tv.w,tv.w);
                    fma2(acc[0],  t0, wa.x); fma2(acc[1],  t0, wa.y); fma2(acc[2],  t0, wb.x); fma2(acc[3],  t0, wb.y);
                    fma2(acc[4],  t1, wa.x); fma2(acc[5],  t1, wa.y); fma2(acc[6],  t1, wb.x); fma2(acc[7],  t1, wb.y);
                    fma2(acc[8],  t2, wa.x); fma2(acc[9],  t2, wa.y); fma2(acc[10], t2, wb.x); fma2(acc[11], t2, wb.y);
                    fma2(acc[12], t3, wa.x); fma2(acc[13], t3, wa.y); fma2(acc[14], t3, wb.x); fma2(acc[15], t3, wb.y);
                }
                float gp[4];
                #pragma unroll
                for (int e4=0;e4<4;e4++){
                    float s = 0.f;
                    #pragma unroll
                    for (int jp=0;jp<4;jp++){
                        float2 f = unpack2(acc[e4*4+jp]);
                        s += silu_f(f.x)*s_cw2[og*8+2*jp] + silu_f(f.y)*s_cw2[og*8+2*jp+1];
                    }
                    gp[e4] = s;
                }
                // reduce across og (lanes sharing eg; strides 4,8,16)
                #pragma unroll
                for (int off=4; off<32; off<<=1){
                    #pragma unroll
                    for (int e4=0;e4<4;e4++)
                        gp[e4] += __shfl_xor_sync(FM, gp[e4], off);
                }
                if (og == 0){
                    int i0 = eg*4;
                    int rcur = s_r[i0];
                    float cx = s_dx[i0]*gp[0], cy = s_dy[i0]*gp[0], cz = s_dz[i0]*gp[0];
                    #pragma unroll
                    for (int i=1;i<4;i++){
                        int ri = s_r[i0+i];
                        float gx = s_dx[i0+i]*gp[i], gy = s_dy[i0+i]*gp[i], gz = s_dz[i0+i]*gp[i];
                        if (ri == rcur){ cx += gx; cy += gy; cz += gz; }
                        else {
                            red4(&g_cagg4[rcur*4], cx, cy, cz, 0.f);
                            rcur = ri; cx = gx; cy = gy; cz = gz;
                        }
                    }
                    red4(&g_cagg4[rcur*4], cx, cy, cz, 0.f);
                }
            }
            __syncwarp();   // protect s_t/s_r before next subtile's P1
        }
        if (lane == 0) base = atomicAdd(&g_tile, 1);
        base = __shfl_sync(FM, base, 0);
    }
}

// -------- fused node MLP + state update ------------------------------------------
__global__ void k_node(const float* __restrict__ n_w1, const float* __restrict__ n_b1,
                       const float* __restrict__ n_w2, const float* __restrict__ n_b2){
    extern __shared__ float sn[];
    float* s_w1 = sn;
    float* s_w2 = sn + 8192;
    float* s_b1 = sn + 12288;
    float* s_b2 = sn + 12352;
    int tid = threadIdx.x;
    for (int i=tid; i<8192; i+=blockDim.x) s_w1[i] = n_w1[i];
    for (int i=tid; i<4096; i+=blockDim.x) s_w2[i] = n_w2[i];
    if (tid < 64){ s_b1[tid]=n_b1[tid]; s_b2[tid]=n_b2[tid]; }
    __syncthreads();
    int lane = tid & 31, warp = tid >> 5;
    int j0 = 2*lane;
    int wpb = blockDim.x >> 5;
    for (int n = blockIdx.x*wpb + warp; n < NN; n += gridDim.x*wpb){
        float h0 = g_h[n*H+j0],    h1 = g_h[n*H+j0+1];
        float m0 = g_magg[n*H+j0], m1 = g_magg[n*H+j0+1];
        float u0 = s_b1[j0], u1 = s_b1[j0+1];
        #pragma unroll
        for (int k=0;k<H;k++){
            float hk = __shfl_sync(0xffffffffu, (k&1)?h1:h0, k>>1);
            float mk = __shfl_sync(0xffffffffu, (k&1)?m1:m0, k>>1);
            float2 wv1 = *(const float2*)&s_w1[k*H+j0];
            float2 wv2 = *(const float2*)&s_w1[(H+k)*H+j0];
            u0 += hk*wv1.x + mk*wv2.x;
            u1 += hk*wv1.y + mk*wv2.y;
        }
        u0 = silu_f(u0); u1 = silu_f(u1);
        float a0 = s_b2[j0], a1 = s_b2[j0+1];
        #pragma unroll
        for (int k=0;k<H;k++){
            float uk = __shfl_sync(0xffffffffu, (k&1)?u1:u0, k>>1);
            float2 wv = *(const float2*)&s_w2[k*H+j0];
            a0 += uk*wv.x; a1 += uk*wv.y;
        }
        *(float2*)&g_h[n*H+j0] = make_float2(2.f*h0 + a0, 2.f*h1 + a1);
        if (lane < 3){
            float dg = g_deg[n];
            float cm = g_cagg4[n*4+lane] / dg;
            float vi = g_v4[n*4+lane];
            float vn = vi + cm + g_vel[n]*vi;
            g_v4[n*4+lane] = vn;
            g_x4[n*4+lane] += vn;
        }
    }
}

// ---------------- output: [x | h | v] ---------------------------------------------
__global__ void k_out(float* __restrict__ out){
    int i = blockIdx.x*blockDim.x + threadIdx.x;
    if (i < NN*3){
        int n = i/3, d = i - n*3;
        out[i] = g_x4[n*4+d];
    } else if (i < NN*3+NN*H){
        out[i] = g_h[i-NN*3];
    } else if (i < NN*(6+H)){
        int j = i - NN*3 - NN*H;
        int n = j/3, d = j - n*3;
        out[i] = g_v4[n*4+d];
    }
}

extern "C" void kernel_launch(void* const* d_in, const int* in_sizes, int n_in,
                              void* d_out, int out_size){
    const float* his  = (const float*)d_in[0];
    const float* x    = (const float*)d_in[1];
    const float* v    = (const float*)d_in[2];
    const float* edge_attr = (const float*)d_in[3];
    const int*   edges= (const int*)  d_in[4];
    const float* emb_w= (const float*)d_in[5];
    const float* emb_b= (const float*)d_in[6];
    const float* e_w1 = (const float*)d_in[7];
    const float* e_b1 = (const float*)d_in[8];
    const float* e_w2 = (const float*)d_in[9];
    const float* e_b2 = (const float*)d_in[10];
    const float* c_w1 = (const float*)d_in[11];
    const float* c_b1 = (const float*)d_in[12];
    const float* c_w2 = (const float*)d_in[13];
    const float* n_w1 = (const float*)d_in[14];
    const float* n_b1 = (const float*)d_in[15];
    const float* n_w2 = (const float*)d_in[16];
    const float* n_b2 = (const float*)d_in[17];
    const float* v_w1 = (const float*)d_in[18];
    const float* v_b1 = (const float*)d_in[19];
    const float* v_w2 = (const float*)d_in[20];
    const float* v_b2 = (const float*)d_in[21];

    const int PREVEL_SMEM = 12480*4;
    const int NODE_SMEM   = 12416*4;
    const int EDGE_SMEM   = 17280*4;   // 69120 B
    cudaFuncSetAttribute(k_prevel, cudaFuncAttributeMaxDynamicSharedMemorySize, PREVEL_SMEM);
    cudaFuncSetAttribute(k_node,   cudaFuncAttributeMaxDynamicSharedMemorySize, NODE_SMEM);
    cudaFuncSetAttribute(k_edge,   cudaFuncAttributeMaxDynamicSharedMemorySize, EDGE_SMEM);

    k_init<<<(NN*H+255)/256, 256>>>(his, emb_w, emb_b, x, v);
    k_deg<<<(EE+255)/256, 256>>>(edges);
    k_scan<<<1, 1024>>>();
    k_fill<<<(EE+255)/256, 256>>>(edges, edge_attr);

    const int gn = 444;
    const int ge = 444;    // 148 SMs x 3 blocks; 24 autonomous warps/SM

    for (int l=0; l<3; l++){
        k_prevel<<<gn, 256, PREVEL_SMEM>>>(e_w1, e_b1, v_w1, v_b1, v_w2, v_b2);
        k_edge<<<ge, 256, EDGE_SMEM>>>(e_w1, e_w2, e_b2, c_w1, c_b1, c_w2);
        k_node<<<gn, 256, NODE_SMEM>>>(n_w1, n_b1, n_w2, n_b2);
    }
    k_out<<<(NN*(H+6)+255)/256, 256>>>((float*)d_out);
}